// round 16
// baseline (speedup 1.0000x reference)
#include <cuda_runtime.h>
#include <cuda_bf16.h>
#include <math.h>
#include <stdint.h>

#define Bsz  4
#define Lsz  2048
#define Dsz  512
#define Hn   8
#define HDsz 64
#define NLn  2
#define NT   (Bsz*Lsz)          // 8192 tokens
#define EPSv 1e-5f
#define LOG2E 1.44269504f

// ---------------- scratch (device globals: no allocation allowed) ----------
__device__ float g_x  [NT*Dsz];                // fp32 residual stream
__device__ __nv_bfloat16 g_xnb[NT*Dsz];        // LN output (bf16)
__device__ __nv_bfloat16 g_qb [NT*Dsz];
__device__ __nv_bfloat16 g_kb [NT*Dsz];
__device__ __nv_bfloat16 g_vt [NT*Dsz];        // V transposed [b][h][d][L]
__device__ __nv_bfloat16 g_ctxb[NT*Dsz];       // attention out (bf16)
__device__ __nv_bfloat16 g_gb [NT*Dsz];        // swiglu out (bf16)
#define WL_OFF  1835008
__device__ __nv_bfloat16 g_wb[NLn*WL_OFF];
__device__ const int c_koff[6] = {0, 262144, 524288, 786432, 1048576, 1572864};

// ---------------- weight transpose+convert ----------------------------------
__global__ void wtrans_kernel(const float* __restrict__ Wq, const float* __restrict__ Wk,
                              const float* __restrict__ Wv, const float* __restrict__ Wo,
                              const float* __restrict__ W1, const float* __restrict__ W2,
                              __nv_bfloat16* __restrict__ dst)
{
    __shared__ float tile[32][33];
    int z = blockIdx.z;
    int layer = z / 6, kind = z % 6;
    int N = (kind == 4) ? 1024 : 512;
    int nb = blockIdx.x * 32;
    if (nb >= N) return;
    int kb = blockIdx.y * 32;
    const float* srcs[6] = {Wq, Wk, Wv, Wo, W1, W2};
    const float* src = srcs[kind] + (size_t)layer * 512 * N;
    __nv_bfloat16* d = dst + (size_t)layer * WL_OFF + c_koff[kind];

    int tx = threadIdx.x, ty = threadIdx.y;
    #pragma unroll
    for (int i = 0; i < 4; i++)
        tile[ty + i*8][tx] = src[(size_t)(kb + ty + i*8) * N + nb + tx];
    __syncthreads();
    #pragma unroll
    for (int i = 0; i < 4; i++)
        d[(size_t)(nb + ty + i*8) * 512 + kb + tx] = __float2bfloat16(tile[tx][ty + i*8]);
}

// ---------------- LN (templated output type) --------------------------------
template<bool BF>
__global__ void ln_kernel(const float* __restrict__ x, const float* __restrict__ w,
                          const float* __restrict__ bb, void* __restrict__ y)
{
    int row = blockIdx.x;
    int t   = threadIdx.x;   // 0..127
    float4 v = ((const float4*)(x + (size_t)row*Dsz))[t];
    float s  = v.x + v.y + v.z + v.w;
    float s2 = v.x*v.x + v.y*v.y + v.z*v.z + v.w*v.w;
    #pragma unroll
    for (int o = 16; o; o >>= 1) {
        s  += __shfl_xor_sync(0xffffffffu, s,  o);
        s2 += __shfl_xor_sync(0xffffffffu, s2, o);
    }
    __shared__ float sh[8];
    int wid = t >> 5;
    if ((t & 31) == 0) { sh[wid] = s; sh[4 + wid] = s2; }
    __syncthreads();
    s  = sh[0] + sh[1] + sh[2] + sh[3];
    s2 = sh[4] + sh[5] + sh[6] + sh[7];
    float mu  = s * (1.0f / Dsz);
    float var = s2 * (1.0f / Dsz) - mu * mu;
    float inv = rsqrtf(var + EPSv);
    float4 w4 = ((const float4*)w)[t];
    float4 b4 = ((const float4*)bb)[t];
    float4 o4;
    o4.x = (v.x - mu) * inv * w4.x + b4.x;
    o4.y = (v.y - mu) * inv * w4.y + b4.y;
    o4.z = (v.z - mu) * inv * w4.z + b4.z;
    o4.w = (v.w - mu) * inv * w4.w + b4.w;
    if (BF) {
        __nv_bfloat16* yb = (__nv_bfloat16*)y + (size_t)row*Dsz + t*4;
        *(__nv_bfloat162*)yb       = __floats2bfloat162_rn(o4.x, o4.y);
        *(__nv_bfloat162*)(yb + 2) = __floats2bfloat162_rn(o4.z, o4.w);
    } else {
        ((float4*)((float*)y + (size_t)row*Dsz))[t] = o4;
    }
}

// ---------------- common helpers --------------------------------------------
__device__ __forceinline__ void cp16(void* s, const void* g) {
    unsigned sa = (unsigned)__cvta_generic_to_shared(s);
    asm volatile("cp.async.cg.shared.global [%0], [%1], 16;" :: "r"(sa), "l"(g));
}
__device__ __forceinline__ uint32_t smem_u32(const void* p) {
    return (uint32_t)__cvta_generic_to_shared(p);
}
__device__ __forceinline__ void mma_bf16_16x8x16(float* c, const uint32_t* a,
                                                 uint32_t b0, uint32_t b1) {
    asm volatile(
        "mma.sync.aligned.m16n8k16.row.col.f32.bf16.bf16.f32 "
        "{%0,%1,%2,%3},{%4,%5,%6,%7},{%8,%9},{%0,%1,%2,%3};"
        : "+f"(c[0]), "+f"(c[1]), "+f"(c[2]), "+f"(c[3])
        : "r"(a[0]), "r"(a[1]), "r"(a[2]), "r"(a[3]), "r"(b0), "r"(b1));
}
__device__ __forceinline__ void ldsm_x4(uint32_t* r, uint32_t sa) {
    asm volatile("ldmatrix.sync.aligned.m8n8.x4.shared.b16 {%0,%1,%2,%3}, [%4];"
        : "=r"(r[0]), "=r"(r[1]), "=r"(r[2]), "=r"(r[3]) : "r"(sa));
}
__device__ __forceinline__ void ldsm_x2(uint32_t* r, uint32_t sa) {
    asm volatile("ldmatrix.sync.aligned.m8n8.x2.shared.b16 {%0,%1}, [%2];"
        : "=r"(r[0]), "=r"(r[1]) : "r"(sa));
}
__device__ __forceinline__ uint32_t packbf(float a, float b) {
    __nv_bfloat162 t = __floats2bfloat162_rn(a, b);
    return *(uint32_t*)&t;
}
__device__ __forceinline__ float ex2f(float x) {
    float r; asm("ex2.approx.ftz.f32 %0, %1;" : "=f"(r) : "f"(x)); return r;
}

// ---------------- bf16 tensor-core GEMM: 128x128x64 tiles, 3-stage ----------
#define TBM 128
#define TBN 128
#define TBK 64
#define NSTG 3
#define BST 72                      // bf16 row stride (144 B; banks 4r, conflict-free)
#define BTILE (128*BST)             // 9216 bf16 per tile
#define BSTAGE (2*BTILE)            // 18432 bf16 = 36864 bytes
#define BGEMM_SMEM (NSTG*BSTAGE*2)  // 110592 bytes
#define RT_ST 136

// MODE: 0 fp32 out, 1 fp32 + residual, 2 bf16 out (scaled), 3 bf16 V-transpose,
//       4 bf16 out with fused RoPE (scale applied before rotation)
template<int MODE>
__device__ __forceinline__ void
bgemm_body(const __nv_bfloat16* __restrict__ A, const __nv_bfloat16* __restrict__ Bt,
           const float* __restrict__ Cin, void* __restrict__ Cout,
           int N, int K, __nv_bfloat16* smbuf, int bm, int bn, float outscale,
           const float* __restrict__ cosb, const float* __restrict__ sinb)
{
    int tid = threadIdx.x;
    int wid = tid >> 5, lane = tid & 31;
    int g  = lane >> 2, tg = lane & 3;
    int wm = (wid >> 2) * 64;
    int wn = (wid & 3) * 32;

    int a_row = wm + (lane & 15);
    int a_klo = (lane >> 4) << 3;
    int b_row = wn + (lane & 7);
    int b_klo = ((lane >> 3) & 1) << 3;

    float acc[4][4][4];
    #pragma unroll
    for (int mi = 0; mi < 4; mi++)
        #pragma unroll
        for (int nj = 0; nj < 4; nj++)
            #pragma unroll
            for (int r = 0; r < 4; r++) acc[mi][nj][r] = 0.f;

    int KT = K / TBK;

    auto prefetch = [&](int kt, int s) {
        __nv_bfloat16* As = smbuf + s * BSTAGE;
        __nv_bfloat16* Bs = As + BTILE;
        int k0 = kt * TBK;
        #pragma unroll
        for (int i = 0; i < 4; i++) {
            int c = tid + i * 256;              // 1024 chunks: 128 rows x 8
            int r = c >> 3, q = (c & 7) << 3;
            cp16(As + r * BST + q, A + (size_t)(bm + r) * K + k0 + q);
        }
        #pragma unroll
        for (int i = 0; i < 4; i++) {
            int c = tid + i * 256;
            int r = c >> 3, q = (c & 7) << 3;
            cp16(Bs + r * BST + q, Bt + (size_t)(bn + r) * K + k0 + q);
        }
    };

    prefetch(0, 0);
    asm volatile("cp.async.commit_group;");
    if (KT > 1) prefetch(1, 1);
    asm volatile("cp.async.commit_group;");

    int st = 0;
    for (int kt = 0; kt < KT; kt++) {
        if (kt + 2 < KT) {
            int s2 = (st + 2 >= NSTG) ? st + 2 - NSTG : st + 2;
            prefetch(kt + 2, s2);
            asm volatile("cp.async.commit_group;");
            asm volatile("cp.async.wait_group 2;");
        } else if (kt + 1 < KT) {
            asm volatile("cp.async.wait_group 1;");
        } else {
            asm volatile("cp.async.wait_group 0;");
        }
        __syncthreads();
        const __nv_bfloat16* As = smbuf + st * BSTAGE;
        const __nv_bfloat16* Bs = As + BTILE;
        uint32_t As_u = smem_u32(As);
        uint32_t Bs_u = smem_u32(Bs);

        #pragma unroll
        for (int kc = 0; kc < 4; kc++) {
            uint32_t af[4][4], bf[4][2];
            #pragma unroll
            for (int mi = 0; mi < 4; mi++)
                ldsm_x4(af[mi], As_u + (uint32_t)(((a_row + mi*16) * BST + kc*16 + a_klo) * 2));
            #pragma unroll
            for (int nj = 0; nj < 4; nj++)
                ldsm_x2(bf[nj], Bs_u + (uint32_t)(((b_row + nj*8) * BST + kc*16 + b_klo) * 2));
            #pragma unroll
            for (int mi = 0; mi < 4; mi++)
                #pragma unroll
                for (int nj = 0; nj < 4; nj++)
                    mma_bf16_16x8x16(acc[mi][nj], af[mi], bf[nj][0], bf[nj][1]);
        }
        __syncthreads();
        st = (st + 1 >= NSTG) ? 0 : st + 1;
    }

    if (MODE == 4) {
        __nv_bfloat16* T = smbuf;
        #pragma unroll
        for (int mi = 0; mi < 4; mi++) {
            int lr = wm + mi * 16 + g;
            #pragma unroll
            for (int nj = 0; nj < 4; nj++) {
                int lc = wn + nj * 8 + tg * 2;
                *(__nv_bfloat162*)(T + lr*RT_ST + lc) =
                    __floats2bfloat162_rn(acc[mi][nj][0]*outscale, acc[mi][nj][1]*outscale);
                *(__nv_bfloat162*)(T + (lr+8)*RT_ST + lc) =
                    __floats2bfloat162_rn(acc[mi][nj][2]*outscale, acc[mi][nj][3]*outscale);
            }
        }
        __syncthreads();
        __nv_bfloat16* C = (__nv_bfloat16*)Cout;
        #pragma unroll
        for (int it = 0; it < 8; it++) {
            int item = tid + it * 256;
            int r   = item >> 4;
            int sub = item & 15;
            int hh  = sub & 1;
            int p   = (sub >> 1) << 2;
            int row = bm + r;
            int l   = row & (Lsz - 1);
            __nv_bfloat162 t1a = *(__nv_bfloat162*)(T + r*RT_ST + hh*64 + p);
            __nv_bfloat162 t1b = *(__nv_bfloat162*)(T + r*RT_ST + hh*64 + p + 2);
            __nv_bfloat162 t2a = *(__nv_bfloat162*)(T + r*RT_ST + hh*64 + p + 32);
            __nv_bfloat162 t2b = *(__nv_bfloat162*)(T + r*RT_ST + hh*64 + p + 34);
            float a0 = __bfloat162float(t1a.x), a1 = __bfloat162float(t1a.y);
            float a2 = __bfloat162float(t1b.x), a3 = __bfloat162float(t1b.y);
            float b0 = __bfloat162float(t2a.x), b1 = __bfloat162float(t2a.y);
            float b2 = __bfloat162float(t2b.x), b3 = __bfloat162float(t2b.y);
            float4 c1 = *(const float4*)(cosb + (size_t)l*Dsz + p);
            float4 c2 = *(const float4*)(cosb + (size_t)l*Dsz + p + 32);
            float4 s1 = *(const float4*)(sinb + (size_t)l*Dsz + p);
            float4 s2 = *(const float4*)(sinb + (size_t)l*Dsz + p + 32);
            float o10 = a0*c1.x - b0*s1.x, o20 = b0*c2.x + a0*s2.x;
            float o11 = a1*c1.y - b1*s1.y, o21 = b1*c2.y + a1*s2.y;
            float o12 = a2*c1.z - b2*s1.z, o22 = b2*c2.z + a2*s2.z;
            float o13 = a3*c1.w - b3*s1.w, o23 = b3*c2.w + a3*s2.w;
            __nv_bfloat16* op = C + (size_t)row * 512 + bn + hh*64 + p;
            *(__nv_bfloat162*)op        = __floats2bfloat162_rn(o10, o11);
            *(__nv_bfloat162*)(op + 2)  = __floats2bfloat162_rn(o12, o13);
            *(__nv_bfloat162*)(op + 32) = __floats2bfloat162_rn(o20, o21);
            *(__nv_bfloat162*)(op + 34) = __floats2bfloat162_rn(o22, o23);
        }
        return;
    }

    #pragma unroll
    for (int mi = 0; mi < 4; mi++) {
        int r0 = bm + wm + mi * 16 + g;
        #pragma unroll
        for (int nj = 0; nj < 4; nj++) {
            int cc = bn + wn + nj * 8 + tg * 2;
            float2 v0 = make_float2(acc[mi][nj][0], acc[mi][nj][1]);
            float2 v1 = make_float2(acc[mi][nj][2], acc[mi][nj][3]);
            if (MODE == 1) {
                float2 p0 = *(const float2*)(Cin + (size_t)r0 * N + cc);
                float2 p1 = *(const float2*)(Cin + (size_t)(r0 + 8) * N + cc);
                v0.x += p0.x; v0.y += p0.y; v1.x += p1.x; v1.y += p1.y;
            }
            if (MODE <= 1) {
                float* C = (float*)Cout;
                *(float2*)(C + (size_t)r0 * N + cc)       = v0;
                *(float2*)(C + (size_t)(r0 + 8) * N + cc) = v1;
            } else if (MODE == 2) {
                __nv_bfloat16* C = (__nv_bfloat16*)Cout;
                *(__nv_bfloat162*)(C + (size_t)r0 * N + cc) =
                    __floats2bfloat162_rn(v0.x * outscale, v0.y * outscale);
                *(__nv_bfloat162*)(C + (size_t)(r0 + 8) * N + cc) =
                    __floats2bfloat162_rn(v1.x * outscale, v1.y * outscale);
            } else {  // MODE 3: transposed bf16 [b][h][d][L]
                __nv_bfloat16* C = (__nv_bfloat16*)Cout;
                int b0i = r0 >> 11, l0 = r0 & 2047;
                int b1i = (r0 + 8) >> 11, l1 = (r0 + 8) & 2047;
                int h0 = cc >> 6, d0 = cc & 63;
                int h1 = (cc + 1) >> 6, d1 = (cc + 1) & 63;
                C[((size_t)(b0i*Hn + h0)*HDsz + d0)*Lsz + l0] = __float2bfloat16(v0.x);
                C[((size_t)(b0i*Hn + h1)*HDsz + d1)*Lsz + l0] = __float2bfloat16(v0.y);
                C[((size_t)(b1i*Hn + h0)*HDsz + d0)*Lsz + l1] = __float2bfloat16(v1.x);
                C[((size_t)(b1i*Hn + h1)*HDsz + d1)*Lsz + l1] = __float2bfloat16(v1.y);
            }
        }
    }
}

template<int MODE>
__global__ void __launch_bounds__(256, 2)
bgemm(const __nv_bfloat16* __restrict__ A, const __nv_bfloat16* __restrict__ Bt,
      const float* __restrict__ Cin, void* __restrict__ C, int N, int K)
{
    extern __shared__ __nv_bfloat16 smbufb[];
    bgemm_body<MODE>(A, Bt, Cin, C, N, K, smbufb, blockIdx.y * TBM, blockIdx.x * TBN,
                     1.f, nullptr, nullptr);
}

// Q, K, V projections + fused RoPE (Q carries 0.125*log2e for exp2 softmax)
__global__ void __launch_bounds__(256, 2)
bgemm_qkv(const __nv_bfloat16* __restrict__ A, const __nv_bfloat16* __restrict__ wb,
          __nv_bfloat16* __restrict__ Cq, __nv_bfloat16* __restrict__ Ck,
          __nv_bfloat16* __restrict__ Cv,
          const float* __restrict__ cosb, const float* __restrict__ sinb,
          int N, int K)
{
    extern __shared__ __nv_bfloat16 smbufb[];
    int z = blockIdx.z;
    const __nv_bfloat16* Bt = wb + (size_t)z * 262144;
    if (z == 0)
        bgemm_body<4>(A, Bt, nullptr, Cq, N, K, smbufb, blockIdx.y*TBM, blockIdx.x*TBN,
                      0.125f * LOG2E, cosb, sinb);
    else if (z == 1)
        bgemm_body<4>(A, Bt, nullptr, Ck, N, K, smbufb, blockIdx.y*TBM, blockIdx.x*TBN,
                      1.f, cosb, sinb);
    else
        bgemm_body<3>(A, Bt, nullptr, Cv, N, K, smbufb, blockIdx.y*TBM, blockIdx.x*TBN,
                      1.f, nullptr, nullptr);
}

// ---------------- fused W1 + SwiGLU (bf16) -----------------------------------
__global__ void __launch_bounds__(256, 2)
bgemm_swiglu(const __nv_bfloat16* __restrict__ A, const __nv_bfloat16* __restrict__ W1t,
             __nv_bfloat16* __restrict__ G, int K)
{
    extern __shared__ __nv_bfloat16 smbufb[];
    int bm  = blockIdx.y * TBM;
    int bn2 = blockIdx.x * 64;
    int tid = threadIdx.x;
    int wid = tid >> 5, lane = tid & 31;
    int g  = lane >> 2, tg = lane & 3;
    int wm = (wid >> 2) * 64;
    int wn = (wid & 3) * 16;

    int a_row = wm + (lane & 15);
    int a_klo = (lane >> 4) << 3;
    int b_row = lane & 7;
    int b_klo = ((lane >> 3) & 1) << 3;

    float acc[4][4][4];
    #pragma unroll
    for (int mi = 0; mi < 4; mi++)
        #pragma unroll
        for (int nj = 0; nj < 4; nj++)
            #pragma unroll
            for (int r = 0; r < 4; r++) acc[mi][nj][r] = 0.f;

    int KT = K / TBK;

    auto prefetch = [&](int kt, int s) {
        __nv_bfloat16* As = smbufb + s * BSTAGE;
        __nv_bfloat16* Bs = As + BTILE;
        int k0 = kt * TBK;
        #pragma unroll
        for (int i = 0; i < 4; i++) {
            int c = tid + i * 256;
            int r = c >> 3, q = (c & 7) << 3;
            cp16(As + r * BST + q, A + (size_t)(bm + r) * K + k0 + q);
        }
        #pragma unroll
        for (int i = 0; i < 4; i++) {
            int c = tid + i * 256;
            int r = c >> 3, q = (c & 7) << 3;
            int grow = (r < 64) ? (bn2 + r) : (512 + bn2 + r - 64);
            cp16(Bs + r * BST + q, W1t + (size_t)grow * K + k0 + q);
        }
    };

    prefetch(0, 0);
    asm volatile("cp.async.commit_group;");
    if (KT > 1) prefetch(1, 1);
    asm volatile("cp.async.commit_group;");

    int st = 0;
    for (int kt = 0; kt < KT; kt++) {
        if (kt + 2 < KT) {
            int s2 = (st + 2 >= NSTG) ? st + 2 - NSTG : st + 2;
            prefetch(kt + 2, s2);
            asm volatile("cp.async.commit_group;");
            asm volatile("cp.async.wait_group 2;");
        } else if (kt + 1 < KT) {
            asm volatile("cp.async.wait_group 1;");
        } else {
            asm volatile("cp.async.wait_group 0;");
        }
        __syncthreads();
        const __nv_bfloat16* As = smbufb + st * BSTAGE;
        const __nv_bfloat16* Bs = As + BTILE;
        uint32_t As_u = smem_u32(As);
        uint32_t Bs_u = smem_u32(Bs);

        #pragma unroll
        for (int kc = 0; kc < 4; kc++) {
            uint32_t af[4][4], bf[4][2];
            #pragma unroll
            for (int mi = 0; mi < 4; mi++)
                ldsm_x4(af[mi], As_u + (uint32_t)(((a_row + mi*16) * BST + kc*16 + a_klo) * 2));
            #pragma unroll
            for (int nj = 0; nj < 4; nj++) {
                int ct = (nj < 2) ? (wn + nj*8) : (64 + wn + (nj - 2)*8);
                ldsm_x2(bf[nj], Bs_u + (uint32_t)(((ct + b_row) * BST + kc*16 + b_klo) * 2));
            }
            #pragma unroll
            for (int mi = 0; mi < 4; mi++)
                #pragma unroll
                for (int nj = 0; nj < 4; nj++)
                    mma_bf16_16x8x16(acc[mi][nj], af[mi], bf[nj][0], bf[nj][1]);
        }
        __syncthreads();
        st = (st + 1 >= NSTG) ? 0 : st + 1;
    }

    #pragma unroll
    for (int mi = 0; mi < 4; mi++) {
        int r0 = bm + wm + mi * 16 + g;
        #pragma unroll
        for (int nj = 0; nj < 2; nj++) {
            int cc = bn2 + wn + nj * 8 + tg * 2;
            float a0 = acc[mi][nj][0], a1 = acc[mi][nj][1];
            float a2 = acc[mi][nj][2], a3 = acc[mi][nj][3];
            float b0 = acc[mi][nj+2][0], b1 = acc[mi][nj+2][1];
            float b2 = acc[mi][nj+2][2], b3 = acc[mi][nj+2][3];
            float v0 = a0 / (1.f + __expf(-a0)) * b0;
            float v1 = a1 / (1.f + __expf(-a1)) * b1;
            float v2 = a2 / (1.f + __expf(-a2)) * b2;
            float v3 = a3 / (1.f + __expf(-a3)) * b3;
            *(__nv_bfloat162*)(G + (size_t)r0 * Dsz + cc)       = __floats2bfloat162_rn(v0, v1);
            *(__nv_bfloat162*)(G + (size_t)(r0 + 8) * Dsz + cc) = __floats2bfloat162_rn(v2, v3);
        }
    }
}

// ---------------- bf16 flash attention (exp2 + ldmatrix + kc pipeline) ------
#define KSTb 88
#define VSTb 136
#define KTILE (128*KSTb)
#define VTILE (64*VSTb)
#define STG_B ((KTILE+VTILE)*2)
#define MSK_B (2*STG_B)
#define AT_SMEM_BYTES (MSK_B + Lsz*4)
#define NKT (Lsz/128)

__global__ void __launch_bounds__(256, 2)
attn_bf16(const __nv_bfloat16* __restrict__ Q, const __nv_bfloat16* __restrict__ Km,
          const __nv_bfloat16* __restrict__ Vt, const float* __restrict__ mask,
          __nv_bfloat16* __restrict__ O)
{
    extern __shared__ __align__(16) char smraw[];
    float* Msk = (float*)(smraw + MSK_B);

    int bh = blockIdx.y;
    int b  = bh >> 3;
    int h  = bh & 7;
    int q0 = blockIdx.x * 128;
    int tid = threadIdx.x;
    int w = tid >> 5, lane = tid & 31;
    int g = lane >> 2, tg = lane & 3;
    int wq = w >> 1, wk = w & 1;

    int l7  = lane & 7;
    int sel8 = ((lane >> 3) & 1) << 3;   // 0 or 8

    size_t baseBL = (size_t)b * Lsz;

    #pragma unroll
    for (int i = tid; i < Lsz/4; i += 256) {
        float4 m4 = ((const float4*)(mask + baseBL))[i];
        m4.x *= LOG2E; m4.y *= LOG2E; m4.z *= LOG2E; m4.w *= LOG2E;
        ((float4*)Msk)[i] = m4;
    }

    auto prefetchKV = [&](int kt, int stg) {
        const __nv_bfloat16* Kg = Km + (baseBL + kt*128) * Dsz + h*HDsz;
        const __nv_bfloat16* Vg = Vt + ((size_t)bh * HDsz) * Lsz + kt*128;
        __nv_bfloat16* Kst = (__nv_bfloat16*)(smraw + stg * STG_B);
        __nv_bfloat16* Vst = Kst + KTILE;
        #pragma unroll
        for (int i = 0; i < 4; i++) {
            int c = tid + i * 256;
            int r = c >> 3, q8 = (c & 7) << 3;
            cp16(Kst + r*KSTb + q8, Kg + (size_t)r*Dsz + q8);
        }
        #pragma unroll
        for (int i = 0; i < 4; i++) {
            int c = tid + i * 256;
            int r = c >> 4, q8 = (c & 15) << 3;
            cp16(Vst + r*VSTb + q8, Vg + (size_t)r*Lsz + q8);
        }
    };

    prefetchKV(0, 0);
    asm volatile("cp.async.commit_group;");

    uint32_t qf[2][4][4];
    #pragma unroll
    for (int qb = 0; qb < 2; qb++) {
        const __nv_bfloat16* Qp = Q + (baseBL + q0 + wq*32 + qb*16 + g) * Dsz + h*HDsz;
        #pragma unroll
        for (int kk = 0; kk < 4; kk++) {
            qf[qb][kk][0] = *(const uint32_t*)(Qp + kk*16 + 2*tg);
            qf[qb][kk][1] = *(const uint32_t*)(Qp + 8*Dsz + kk*16 + 2*tg);
            qf[qb][kk][2] = *(const uint32_t*)(Qp + kk*16 + 2*tg + 8);
            qf[qb][kk][3] = *(const uint32_t*)(Qp + 8*Dsz + kk*16 + 2*tg + 8);
        }
    }

    float o[2][8][4];
    #pragma unroll
    for (int qb = 0; qb < 2; qb++)
        #pragma unroll
        for (int j = 0; j < 8; j++)
            #pragma unroll
            for (int r = 0; r < 4; r++) o[qb][j][r] = 0.f;
    float lp[2][2] = {{0.f, 0.f}, {0.f, 0.f}};

    for (int kt = 0; kt < NKT; kt++) {
        if (kt + 1 < NKT) {
            prefetchKV(kt + 1, (kt + 1) & 1);
            asm volatile("cp.async.commit_group;");
            asm volatile("cp.async.wait_group 1;");
        } else {
            asm volatile("cp.async.wait_group 0;");
        }
        __syncthreads();
        const __nv_bfloat16* Ks = (const __nv_bfloat16*)(smraw + (kt & 1) * STG_B);
        const __nv_bfloat16* Vs = Ks + KTILE;
        uint32_t Ks_u = smem_u32(Ks);
        uint32_t Vs_u = smem_u32(Vs);

        float s0[2][4], s1[2][4];

        // compute S for key-chunk kc into s0/s1 (16 mmas + 8 ldsm)
        auto computeS = [&](int kc) {
            #pragma unroll
            for (int qb = 0; qb < 2; qb++)
                #pragma unroll
                for (int r = 0; r < 4; r++) { s0[qb][r] = 0.f; s1[qb][r] = 0.f; }
            int keybase = wk*64 + kc*16;
            #pragma unroll
            for (int kk = 0; kk < 4; kk++) {
                uint32_t kb0[2], kb1[2];
                ldsm_x2(kb0, Ks_u + (uint32_t)(((keybase + l7)     * KSTb + kk*16 + sel8) * 2));
                ldsm_x2(kb1, Ks_u + (uint32_t)(((keybase + 8 + l7) * KSTb + kk*16 + sel8) * 2));
                mma_bf16_16x8x16(s0[0], qf[0][kk], kb0[0], kb0[1]);
                mma_bf16_16x8x16(s0[1], qf[1][kk], kb0[0], kb0[1]);
                mma_bf16_16x8x16(s1[0], qf[0][kk], kb1[0], kb1[1]);
                mma_bf16_16x8x16(s1[1], qf[1][kk], kb1[0], kb1[1]);
            }
        };

        computeS(0);
        #pragma unroll
        for (int kc = 0; kc < 4; kc++) {
            int keybase = wk*64 + kc*16;
            float2 mk0 = *(const float2*)(Msk + kt*128 + keybase + 2*tg);
            float2 mk1 = *(const float2*)(Msk + kt*128 + keybase + 8 + 2*tg);

            // exp/pack: converts s -> pf; s registers dead afterwards
            uint32_t pf[2][4];
            #pragma unroll
            for (int qb = 0; qb < 2; qb++) {
                float e00 = ex2f(s0[qb][0] + mk0.x);
                float e01 = ex2f(s0[qb][1] + mk0.y);
                float e02 = ex2f(s0[qb][2] + mk0.x);
                float e03 = ex2f(s0[qb][3] + mk0.y);
                float e10 = ex2f(s1[qb][0] + mk1.x);
                float e11 = ex2f(s1[qb][1] + mk1.y);
                float e12 = ex2f(s1[qb][2] + mk1.x);
                float e13 = ex2f(s1[qb][3] + mk1.y);
                lp[qb][0] += e00 + e01 + e10 + e11;
                lp[qb][1] += e02 + e03 + e12 + e13;
                pf[qb][0] = packbf(e00, e01);
                pf[qb][1] = packbf(e02, e03);
                pf[qb][2] = packbf(e10, e11);
                pf[qb][3] = packbf(e12, e13);
            }

            // overlap: S of next chunk issues while exp chain drains
            if (kc < 3) computeS(kc + 1);

            // O += P V for chunk kc
            #pragma unroll
            for (int j = 0; j < 8; j++) {
                uint32_t vb[2];
                ldsm_x2(vb, Vs_u + (uint32_t)(((j*8 + l7) * VSTb + keybase + sel8) * 2));
                mma_bf16_16x8x16(o[0][j], pf[0], vb[0], vb[1]);
                mma_bf16_16x8x16(o[1][j], pf[1], vb[0], vb[1]);
            }
        }
        __syncthreads();
    }

    #pragma unroll
    for (int qb = 0; qb < 2; qb++)
        #pragma unroll
        for (int r = 0; r < 2; r++) {
            lp[qb][r] += __shfl_xor_sync(0xffffffffu, lp[qb][r], 1);
            lp[qb][r] += __shfl_xor_sync(0xffffffffu, lp[qb][r], 2);
        }

    float* Ex = (float*)smraw;
    if (wk == 1) {
        #pragma unroll
        for (int qb = 0; qb < 2; qb++) {
            float* ep = Ex + (wq*2 + qb) * 1024;
            #pragma unroll
            for (int j = 0; j < 8; j++) {
                *(float2*)(ep + g*64     + j*8 + 2*tg) = make_float2(o[qb][j][0], o[qb][j][1]);
                *(float2*)(ep + (g+8)*64 + j*8 + 2*tg) = make_float2(o[qb][j][2], o[qb][j][3]);
            }
        }
        if (tg == 0) {
            #pragma unroll
            for (int qb = 0; qb < 2; qb++) {
                Msk[wq*32 + qb*16 + g]     = lp[qb][0];
                Msk[wq*32 + qb*16 + g + 8] = lp[qb][1];
            }
        }
    }
    __syncthreads();
    if (wk == 0) {
        #pragma unroll
        for (int qb = 0; qb < 2; qb++) {
            const float* ep = Ex + (wq*2 + qb) * 1024;
            float l0 = lp[qb][0] + Msk[wq*32 + qb*16 + g];
            float l1 = lp[qb][1] + Msk[wq*32 + qb*16 + g + 8];
            float inv0 = 1.f / l0, inv1 = 1.f / l1;
            int row = q0 + wq*32 + qb*16 + g;
            __nv_bfloat16* Op0 = O + (baseBL + row) * Dsz + h*HDsz;
            __nv_bfloat16* Op1 = Op0 + (size_t)8 * Dsz;
            #pragma unroll
            for (int j = 0; j < 8; j++) {
                float2 p0 = *(const float2*)(ep + g*64     + j*8 + 2*tg);
                float2 p1 = *(const float2*)(ep + (g+8)*64 + j*8 + 2*tg);
                *(__nv_bfloat162*)(Op0 + j*8 + 2*tg) =
                    __floats2bfloat162_rn((o[qb][j][0] + p0.x)*inv0, (o[qb][j][1] + p0.y)*inv0);
                *(__nv_bfloat162*)(Op1 + j*8 + 2*tg) =
                    __floats2bfloat162_rn((o[qb][j][2] + p1.x)*inv1, (o[qb][j][3] + p1.y)*inv1);
            }
        }
    }
}

// ---------------- host orchestration ----------------------------------------
extern "C" void kernel_launch(void* const* d_in, const int* in_sizes, int n_in,
                              void* d_out, int out_size)
{
    const float* x    = (const float*)d_in[0];
    const float* pcos = (const float*)d_in[1];
    const float* psin = (const float*)d_in[2];
    const float* mask = (const float*)d_in[3];
    const float* Wq   = (const float*)d_in[4];
    const float* Wk   = (const float*)d_in[5];
    const float* Wv   = (const float*)d_in[6];
    const float* Wo   = (const float*)d_in[7];
    const float* W1   = (const float*)d_in[8];
    const float* W2   = (const float*)d_in[9];
    const float* ln1w = (const float*)d_in[10];
    const float* ln1b = (const float*)d_in[11];
    const float* ln2w = (const float*)d_in[12];
    const float* ln2b = (const float*)d_in[13];
    const float* lnfw = (const float*)d_in[14];
    const float* lnfb = (const float*)d_in[15];
    float* out = (float*)d_out;

    float *gx;
    __nv_bfloat16 *gxn, *gq, *gk, *gvt, *gctx, *gg, *gwb;
    cudaGetSymbolAddress((void**)&gx,   g_x);
    cudaGetSymbolAddress((void**)&gxn,  g_xnb);
    cudaGetSymbolAddress((void**)&gq,   g_qb);
    cudaGetSymbolAddress((void**)&gk,   g_kb);
    cudaGetSymbolAddress((void**)&gvt,  g_vt);
    cudaGetSymbolAddress((void**)&gctx, g_ctxb);
    cudaGetSymbolAddress((void**)&gg,   g_gb);
    cudaGetSymbolAddress((void**)&gwb,  g_wb);

    cudaFuncSetAttribute(attn_bf16, cudaFuncAttributeMaxDynamicSharedMemorySize,
                         AT_SMEM_BYTES);
    cudaFuncSetAttribute(bgemm<1>, cudaFuncAttributeMaxDynamicSharedMemorySize,
                         BGEMM_SMEM);
    cudaFuncSetAttribute(bgemm_qkv, cudaFuncAttributeMaxDynamicSharedMemorySize,
                         BGEMM_SMEM);
    cudaFuncSetAttribute(bgemm_swiglu, cudaFuncAttributeMaxDynamicSharedMemorySize,
                         BGEMM_SMEM);

    wtrans_kernel<<<dim3(32, 16, 12), dim3(32, 8)>>>(Wq, Wk, Wv, Wo, W1, W2, gwb);

    dim3 g512 (Dsz / TBN, NT / TBM);      // (4, 64)
    dim3 gQKV (Dsz / TBN, NT / TBM, 3);   // (4, 64, 3)
    dim3 gSWI (Dsz / 64,  NT / TBM);      // (8, 64)
    dim3 gattn(Lsz / 128, Bsz * Hn);      // (16, 32)

    for (int i = 0; i < NLn; i++) {
        const float* xin = (i == 0) ? x : gx;
        const __nv_bfloat16* wl = gwb + (size_t)i * WL_OFF;
        ln_kernel<true><<<NT, 128>>>(xin, ln1w + i*Dsz, ln1b + i*Dsz, gxn);
        bgemm_qkv<<<gQKV, 256, BGEMM_SMEM>>>(gxn, wl, gq, gk, gvt, pcos, psin, Dsz, Dsz);
        attn_bf16<<<gattn, 256, AT_SMEM_BYTES>>>(gq, gk, gvt, mask, gctx);
        bgemm<1><<<g512, 256, BGEMM_SMEM>>>(gctx, wl + 786432, xin, gx, Dsz, Dsz);
        ln_kernel<true><<<NT, 128>>>(gx, ln2w + i*Dsz, ln2b + i*Dsz, gxn);
        bgemm_swiglu<<<gSWI, 256, BGEMM_SMEM>>>(gxn, wl + 1048576, gg, Dsz);
        bgemm<1><<<g512, 256, BGEMM_SMEM>>>(gg, wl + 1572864, gx, gx, Dsz, Dsz);
    }
    ln_kernel<false><<<NT, 128>>>(gx, lnfw, lnfb, out);
}

// round 17
// speedup vs baseline: 1.0196x; 1.0196x over previous
#include <cuda_runtime.h>
#include <cuda_bf16.h>
#include <math.h>
#include <stdint.h>

#define Bsz  4
#define Lsz  2048
#define Dsz  512
#define Hn   8
#define HDsz 64
#define NLn  2
#define NT   (Bsz*Lsz)          // 8192 tokens
#define EPSv 1e-5f
#define LOG2E 1.44269504f

// ---------------- scratch (device globals: no allocation allowed) ----------
__device__ float g_x  [NT*Dsz];                // fp32 residual stream
__device__ __nv_bfloat16 g_xnb[NT*Dsz];        // LN output (bf16)
__device__ __nv_bfloat16 g_qb [NT*Dsz];
__device__ __nv_bfloat16 g_kb [NT*Dsz];
__device__ __nv_bfloat16 g_vt [NT*Dsz];        // V transposed [b][h][d][L]
__device__ __nv_bfloat16 g_ctxb[NT*Dsz];       // attention out (bf16)
__device__ __nv_bfloat16 g_gb [NT*Dsz];        // swiglu out (bf16)
#define WL_OFF  1835008
__device__ __nv_bfloat16 g_wb[NLn*WL_OFF];
__device__ const int c_koff[6] = {0, 262144, 524288, 786432, 1048576, 1572864};

// ---------------- weight transpose+convert ----------------------------------
__global__ void wtrans_kernel(const float* __restrict__ Wq, const float* __restrict__ Wk,
                              const float* __restrict__ Wv, const float* __restrict__ Wo,
                              const float* __restrict__ W1, const float* __restrict__ W2,
                              __nv_bfloat16* __restrict__ dst)
{
    __shared__ float tile[32][33];
    int z = blockIdx.z;
    int layer = z / 6, kind = z % 6;
    int N = (kind == 4) ? 1024 : 512;
    int nb = blockIdx.x * 32;
    if (nb >= N) return;
    int kb = blockIdx.y * 32;
    const float* srcs[6] = {Wq, Wk, Wv, Wo, W1, W2};
    const float* src = srcs[kind] + (size_t)layer * 512 * N;
    __nv_bfloat16* d = dst + (size_t)layer * WL_OFF + c_koff[kind];

    int tx = threadIdx.x, ty = threadIdx.y;
    #pragma unroll
    for (int i = 0; i < 4; i++)
        tile[ty + i*8][tx] = src[(size_t)(kb + ty + i*8) * N + nb + tx];
    __syncthreads();
    #pragma unroll
    for (int i = 0; i < 4; i++)
        d[(size_t)(nb + ty + i*8) * 512 + kb + tx] = __float2bfloat16(tile[tx][ty + i*8]);
}

// ---------------- LN (templated output type) --------------------------------
template<bool BF>
__global__ void ln_kernel(const float* __restrict__ x, const float* __restrict__ w,
                          const float* __restrict__ bb, void* __restrict__ y)
{
    int row = blockIdx.x;
    int t   = threadIdx.x;   // 0..127
    float4 v = ((const float4*)(x + (size_t)row*Dsz))[t];
    float s  = v.x + v.y + v.z + v.w;
    float s2 = v.x*v.x + v.y*v.y + v.z*v.z + v.w*v.w;
    #pragma unroll
    for (int o = 16; o; o >>= 1) {
        s  += __shfl_xor_sync(0xffffffffu, s,  o);
        s2 += __shfl_xor_sync(0xffffffffu, s2, o);
    }
    __shared__ float sh[8];
    int wid = t >> 5;
    if ((t & 31) == 0) { sh[wid] = s; sh[4 + wid] = s2; }
    __syncthreads();
    s  = sh[0] + sh[1] + sh[2] + sh[3];
    s2 = sh[4] + sh[5] + sh[6] + sh[7];
    float mu  = s * (1.0f / Dsz);
    float var = s2 * (1.0f / Dsz) - mu * mu;
    float inv = rsqrtf(var + EPSv);
    float4 w4 = ((const float4*)w)[t];
    float4 b4 = ((const float4*)bb)[t];
    float4 o4;
    o4.x = (v.x - mu) * inv * w4.x + b4.x;
    o4.y = (v.y - mu) * inv * w4.y + b4.y;
    o4.z = (v.z - mu) * inv * w4.z + b4.z;
    o4.w = (v.w - mu) * inv * w4.w + b4.w;
    if (BF) {
        __nv_bfloat16* yb = (__nv_bfloat16*)y + (size_t)row*Dsz + t*4;
        *(__nv_bfloat162*)yb       = __floats2bfloat162_rn(o4.x, o4.y);
        *(__nv_bfloat162*)(yb + 2) = __floats2bfloat162_rn(o4.z, o4.w);
    } else {
        ((float4*)((float*)y + (size_t)row*Dsz))[t] = o4;
    }
}

// ---------------- common helpers --------------------------------------------
__device__ __forceinline__ void cp16(void* s, const void* g) {
    unsigned sa = (unsigned)__cvta_generic_to_shared(s);
    asm volatile("cp.async.cg.shared.global [%0], [%1], 16;" :: "r"(sa), "l"(g));
}
__device__ __forceinline__ uint32_t smem_u32(const void* p) {
    return (uint32_t)__cvta_generic_to_shared(p);
}
__device__ __forceinline__ void mma_bf16_16x8x16(float* c, const uint32_t* a,
                                                 uint32_t b0, uint32_t b1) {
    asm volatile(
        "mma.sync.aligned.m16n8k16.row.col.f32.bf16.bf16.f32 "
        "{%0,%1,%2,%3},{%4,%5,%6,%7},{%8,%9},{%0,%1,%2,%3};"
        : "+f"(c[0]), "+f"(c[1]), "+f"(c[2]), "+f"(c[3])
        : "r"(a[0]), "r"(a[1]), "r"(a[2]), "r"(a[3]), "r"(b0), "r"(b1));
}
__device__ __forceinline__ void ldsm_x4(uint32_t* r, uint32_t sa) {
    asm volatile("ldmatrix.sync.aligned.m8n8.x4.shared.b16 {%0,%1,%2,%3}, [%4];"
        : "=r"(r[0]), "=r"(r[1]), "=r"(r[2]), "=r"(r[3]) : "r"(sa));
}
__device__ __forceinline__ void ldsm_x2(uint32_t* r, uint32_t sa) {
    asm volatile("ldmatrix.sync.aligned.m8n8.x2.shared.b16 {%0,%1}, [%2];"
        : "=r"(r[0]), "=r"(r[1]) : "r"(sa));
}
__device__ __forceinline__ uint32_t packbf(float a, float b) {
    __nv_bfloat162 t = __floats2bfloat162_rn(a, b);
    return *(uint32_t*)&t;
}
__device__ __forceinline__ float ex2f(float x) {
    float r; asm("ex2.approx.ftz.f32 %0, %1;" : "=f"(r) : "f"(x)); return r;
}

// ---------------- bf16 tensor-core GEMM: 128x128x64 tiles, 3-stage ----------
// one __syncthreads per k-tile: prefetch issued AFTER the barrier (all warps
// have finished reading the target stage two tiles ago).
#define TBM 128
#define TBN 128
#define TBK 64
#define NSTG 3
#define BST 72                      // bf16 row stride (144 B; banks 4r, conflict-free)
#define BTILE (128*BST)             // 9216 bf16 per tile
#define BSTAGE (2*BTILE)            // 18432 bf16 = 36864 bytes
#define BGEMM_SMEM (NSTG*BSTAGE*2)  // 110592 bytes
#define RT_ST 136

// MODE: 0 fp32 out, 1 fp32 + residual, 2 bf16 out (scaled), 3 bf16 V-transpose,
//       4 bf16 out with fused RoPE (scale applied before rotation)
template<int MODE>
__device__ __forceinline__ void
bgemm_body(const __nv_bfloat16* __restrict__ A, const __nv_bfloat16* __restrict__ Bt,
           const float* __restrict__ Cin, void* __restrict__ Cout,
           int N, int K, __nv_bfloat16* smbuf, int bm, int bn, float outscale,
           const float* __restrict__ cosb, const float* __restrict__ sinb)
{
    int tid = threadIdx.x;
    int wid = tid >> 5, lane = tid & 31;
    int g  = lane >> 2, tg = lane & 3;
    int wm = (wid >> 2) * 64;
    int wn = (wid & 3) * 32;

    int a_row = wm + (lane & 15);
    int a_klo = (lane >> 4) << 3;
    int b_row = wn + (lane & 7);
    int b_klo = ((lane >> 3) & 1) << 3;

    float acc[4][4][4];
    #pragma unroll
    for (int mi = 0; mi < 4; mi++)
        #pragma unroll
        for (int nj = 0; nj < 4; nj++)
            #pragma unroll
            for (int r = 0; r < 4; r++) acc[mi][nj][r] = 0.f;

    int KT = K / TBK;

    auto prefetch = [&](int kt, int s) {
        __nv_bfloat16* As = smbuf + s * BSTAGE;
        __nv_bfloat16* Bs = As + BTILE;
        int k0 = kt * TBK;
        #pragma unroll
        for (int i = 0; i < 4; i++) {
            int c = tid + i * 256;              // 1024 chunks: 128 rows x 8
            int r = c >> 3, q = (c & 7) << 3;
            cp16(As + r * BST + q, A + (size_t)(bm + r) * K + k0 + q);
        }
        #pragma unroll
        for (int i = 0; i < 4; i++) {
            int c = tid + i * 256;
            int r = c >> 3, q = (c & 7) << 3;
            cp16(Bs + r * BST + q, Bt + (size_t)(bn + r) * K + k0 + q);
        }
    };

    prefetch(0, 0);
    asm volatile("cp.async.commit_group;");
    if (KT > 1) prefetch(1, 1);
    asm volatile("cp.async.commit_group;");

    int st = 0;
    for (int kt = 0; kt < KT; kt++) {
        if (kt + 1 < KT) asm volatile("cp.async.wait_group 1;");
        else             asm volatile("cp.async.wait_group 0;");
        __syncthreads();
        if (kt + 2 < KT) {
            int s2 = (st + 2 >= NSTG) ? st + 2 - NSTG : st + 2;
            prefetch(kt + 2, s2);
            asm volatile("cp.async.commit_group;");
        }
        const __nv_bfloat16* As = smbuf + st * BSTAGE;
        const __nv_bfloat16* Bs = As + BTILE;
        uint32_t As_u = smem_u32(As);
        uint32_t Bs_u = smem_u32(Bs);

        #pragma unroll
        for (int kc = 0; kc < 4; kc++) {
            uint32_t af[4][4], bf[4][2];
            #pragma unroll
            for (int mi = 0; mi < 4; mi++)
                ldsm_x4(af[mi], As_u + (uint32_t)(((a_row + mi*16) * BST + kc*16 + a_klo) * 2));
            #pragma unroll
            for (int nj = 0; nj < 4; nj++)
                ldsm_x2(bf[nj], Bs_u + (uint32_t)(((b_row + nj*8) * BST + kc*16 + b_klo) * 2));
            #pragma unroll
            for (int mi = 0; mi < 4; mi++)
                #pragma unroll
                for (int nj = 0; nj < 4; nj++)
                    mma_bf16_16x8x16(acc[mi][nj], af[mi], bf[nj][0], bf[nj][1]);
        }
        st = (st + 1 >= NSTG) ? 0 : st + 1;
    }

    if (MODE == 4) {
        __syncthreads();   // all warps done with final stage before T reuse
        __nv_bfloat16* T = smbuf;
        #pragma unroll
        for (int mi = 0; mi < 4; mi++) {
            int lr = wm + mi * 16 + g;
            #pragma unroll
            for (int nj = 0; nj < 4; nj++) {
                int lc = wn + nj * 8 + tg * 2;
                *(__nv_bfloat162*)(T + lr*RT_ST + lc) =
                    __floats2bfloat162_rn(acc[mi][nj][0]*outscale, acc[mi][nj][1]*outscale);
                *(__nv_bfloat162*)(T + (lr+8)*RT_ST + lc) =
                    __floats2bfloat162_rn(acc[mi][nj][2]*outscale, acc[mi][nj][3]*outscale);
            }
        }
        __syncthreads();
        __nv_bfloat16* C = (__nv_bfloat16*)Cout;
        #pragma unroll
        for (int it = 0; it < 8; it++) {
            int item = tid + it * 256;
            int r   = item >> 4;
            int sub = item & 15;
            int hh  = sub & 1;
            int p   = (sub >> 1) << 2;
            int row = bm + r;
            int l   = row & (Lsz - 1);
            __nv_bfloat162 t1a = *(__nv_bfloat162*)(T + r*RT_ST + hh*64 + p);
            __nv_bfloat162 t1b = *(__nv_bfloat162*)(T + r*RT_ST + hh*64 + p + 2);
            __nv_bfloat162 t2a = *(__nv_bfloat162*)(T + r*RT_ST + hh*64 + p + 32);
            __nv_bfloat162 t2b = *(__nv_bfloat162*)(T + r*RT_ST + hh*64 + p + 34);
            float a0 = __bfloat162float(t1a.x), a1 = __bfloat162float(t1a.y);
            float a2 = __bfloat162float(t1b.x), a3 = __bfloat162float(t1b.y);
            float b0 = __bfloat162float(t2a.x), b1 = __bfloat162float(t2a.y);
            float b2 = __bfloat162float(t2b.x), b3 = __bfloat162float(t2b.y);
            float4 c1 = *(const float4*)(cosb + (size_t)l*Dsz + p);
            float4 c2 = *(const float4*)(cosb + (size_t)l*Dsz + p + 32);
            float4 s1 = *(const float4*)(sinb + (size_t)l*Dsz + p);
            float4 s2 = *(const float4*)(sinb + (size_t)l*Dsz + p + 32);
            float o10 = a0*c1.x - b0*s1.x, o20 = b0*c2.x + a0*s2.x;
            float o11 = a1*c1.y - b1*s1.y, o21 = b1*c2.y + a1*s2.y;
            float o12 = a2*c1.z - b2*s1.z, o22 = b2*c2.z + a2*s2.z;
            float o13 = a3*c1.w - b3*s1.w, o23 = b3*c2.w + a3*s2.w;
            __nv_bfloat16* op = C + (size_t)row * 512 + bn + hh*64 + p;
            *(__nv_bfloat162*)op        = __floats2bfloat162_rn(o10, o11);
            *(__nv_bfloat162*)(op + 2)  = __floats2bfloat162_rn(o12, o13);
            *(__nv_bfloat162*)(op + 32) = __floats2bfloat162_rn(o20, o21);
            *(__nv_bfloat162*)(op + 34) = __floats2bfloat162_rn(o22, o23);
        }
        return;
    }

    #pragma unroll
    for (int mi = 0; mi < 4; mi++) {
        int r0 = bm + wm + mi * 16 + g;
        #pragma unroll
        for (int nj = 0; nj < 4; nj++) {
            int cc = bn + wn + nj * 8 + tg * 2;
            float2 v0 = make_float2(acc[mi][nj][0], acc[mi][nj][1]);
            float2 v1 = make_float2(acc[mi][nj][2], acc[mi][nj][3]);
            if (MODE == 1) {
                float2 p0 = *(const float2*)(Cin + (size_t)r0 * N + cc);
                float2 p1 = *(const float2*)(Cin + (size_t)(r0 + 8) * N + cc);
                v0.x += p0.x; v0.y += p0.y; v1.x += p1.x; v1.y += p1.y;
            }
            if (MODE <= 1) {
                float* C = (float*)Cout;
                *(float2*)(C + (size_t)r0 * N + cc)       = v0;
                *(float2*)(C + (size_t)(r0 + 8) * N + cc) = v1;
            } else if (MODE == 2) {
                __nv_bfloat16* C = (__nv_bfloat16*)Cout;
                *(__nv_bfloat162*)(C + (size_t)r0 * N + cc) =
                    __floats2bfloat162_rn(v0.x * outscale, v0.y * outscale);
                *(__nv_bfloat162*)(C + (size_t)(r0 + 8) * N + cc) =
                    __floats2bfloat162_rn(v1.x * outscale, v1.y * outscale);
            } else {  // MODE 3: transposed bf16 [b][h][d][L]
                __nv_bfloat16* C = (__nv_bfloat16*)Cout;
                int b0i = r0 >> 11, l0 = r0 & 2047;
                int b1i = (r0 + 8) >> 11, l1 = (r0 + 8) & 2047;
                int h0 = cc >> 6, d0 = cc & 63;
                int h1 = (cc + 1) >> 6, d1 = (cc + 1) & 63;
                C[((size_t)(b0i*Hn + h0)*HDsz + d0)*Lsz + l0] = __float2bfloat16(v0.x);
                C[((size_t)(b0i*Hn + h1)*HDsz + d1)*Lsz + l0] = __float2bfloat16(v0.y);
                C[((size_t)(b1i*Hn + h0)*HDsz + d0)*Lsz + l1] = __float2bfloat16(v1.x);
                C[((size_t)(b1i*Hn + h1)*HDsz + d1)*Lsz + l1] = __float2bfloat16(v1.y);
            }
        }
    }
}

template<int MODE>
__global__ void __launch_bounds__(256, 2)
bgemm(const __nv_bfloat16* __restrict__ A, const __nv_bfloat16* __restrict__ Bt,
      const float* __restrict__ Cin, void* __restrict__ C, int N, int K)
{
    extern __shared__ __nv_bfloat16 smbufb[];
    bgemm_body<MODE>(A, Bt, Cin, C, N, K, smbufb, blockIdx.y * TBM, blockIdx.x * TBN,
                     1.f, nullptr, nullptr);
}

// Q, K, V projections + fused RoPE (Q carries 0.125*log2e for exp2 softmax)
__global__ void __launch_bounds__(256, 2)
bgemm_qkv(const __nv_bfloat16* __restrict__ A, const __nv_bfloat16* __restrict__ wb,
          __nv_bfloat16* __restrict__ Cq, __nv_bfloat16* __restrict__ Ck,
          __nv_bfloat16* __restrict__ Cv,
          const float* __restrict__ cosb, const float* __restrict__ sinb,
          int N, int K)
{
    extern __shared__ __nv_bfloat16 smbufb[];
    int z = blockIdx.z;
    const __nv_bfloat16* Bt = wb + (size_t)z * 262144;
    if (z == 0)
        bgemm_body<4>(A, Bt, nullptr, Cq, N, K, smbufb, blockIdx.y*TBM, blockIdx.x*TBN,
                      0.125f * LOG2E, cosb, sinb);
    else if (z == 1)
        bgemm_body<4>(A, Bt, nullptr, Ck, N, K, smbufb, blockIdx.y*TBM, blockIdx.x*TBN,
                      1.f, cosb, sinb);
    else
        bgemm_body<3>(A, Bt, nullptr, Cv, N, K, smbufb, blockIdx.y*TBM, blockIdx.x*TBN,
                      1.f, nullptr, nullptr);
}

// ---------------- fused W1 + SwiGLU (bf16) -----------------------------------
__global__ void __launch_bounds__(256, 2)
bgemm_swiglu(const __nv_bfloat16* __restrict__ A, const __nv_bfloat16* __restrict__ W1t,
             __nv_bfloat16* __restrict__ G, int K)
{
    extern __shared__ __nv_bfloat16 smbufb[];
    int bm  = blockIdx.y * TBM;
    int bn2 = blockIdx.x * 64;
    int tid = threadIdx.x;
    int wid = tid >> 5, lane = tid & 31;
    int g  = lane >> 2, tg = lane & 3;
    int wm = (wid >> 2) * 64;
    int wn = (wid & 3) * 16;

    int a_row = wm + (lane & 15);
    int a_klo = (lane >> 4) << 3;
    int b_row = lane & 7;
    int b_klo = ((lane >> 3) & 1) << 3;

    float acc[4][4][4];
    #pragma unroll
    for (int mi = 0; mi < 4; mi++)
        #pragma unroll
        for (int nj = 0; nj < 4; nj++)
            #pragma unroll
            for (int r = 0; r < 4; r++) acc[mi][nj][r] = 0.f;

    int KT = K / TBK;

    auto prefetch = [&](int kt, int s) {
        __nv_bfloat16* As = smbufb + s * BSTAGE;
        __nv_bfloat16* Bs = As + BTILE;
        int k0 = kt * TBK;
        #pragma unroll
        for (int i = 0; i < 4; i++) {
            int c = tid + i * 256;
            int r = c >> 3, q = (c & 7) << 3;
            cp16(As + r * BST + q, A + (size_t)(bm + r) * K + k0 + q);
        }
        #pragma unroll
        for (int i = 0; i < 4; i++) {
            int c = tid + i * 256;
            int r = c >> 3, q = (c & 7) << 3;
            int grow = (r < 64) ? (bn2 + r) : (512 + bn2 + r - 64);
            cp16(Bs + r * BST + q, W1t + (size_t)grow * K + k0 + q);
        }
    };

    prefetch(0, 0);
    asm volatile("cp.async.commit_group;");
    if (KT > 1) prefetch(1, 1);
    asm volatile("cp.async.commit_group;");

    int st = 0;
    for (int kt = 0; kt < KT; kt++) {
        if (kt + 1 < KT) asm volatile("cp.async.wait_group 1;");
        else             asm volatile("cp.async.wait_group 0;");
        __syncthreads();
        if (kt + 2 < KT) {
            int s2 = (st + 2 >= NSTG) ? st + 2 - NSTG : st + 2;
            prefetch(kt + 2, s2);
            asm volatile("cp.async.commit_group;");
        }
        const __nv_bfloat16* As = smbufb + st * BSTAGE;
        const __nv_bfloat16* Bs = As + BTILE;
        uint32_t As_u = smem_u32(As);
        uint32_t Bs_u = smem_u32(Bs);

        #pragma unroll
        for (int kc = 0; kc < 4; kc++) {
            uint32_t af[4][4], bf[4][2];
            #pragma unroll
            for (int mi = 0; mi < 4; mi++)
                ldsm_x4(af[mi], As_u + (uint32_t)(((a_row + mi*16) * BST + kc*16 + a_klo) * 2));
            #pragma unroll
            for (int nj = 0; nj < 4; nj++) {
                int ct = (nj < 2) ? (wn + nj*8) : (64 + wn + (nj - 2)*8);
                ldsm_x2(bf[nj], Bs_u + (uint32_t)(((ct + b_row) * BST + kc*16 + b_klo) * 2));
            }
            #pragma unroll
            for (int mi = 0; mi < 4; mi++)
                #pragma unroll
                for (int nj = 0; nj < 4; nj++)
                    mma_bf16_16x8x16(acc[mi][nj], af[mi], bf[nj][0], bf[nj][1]);
        }
        st = (st + 1 >= NSTG) ? 0 : st + 1;
    }

    #pragma unroll
    for (int mi = 0; mi < 4; mi++) {
        int r0 = bm + wm + mi * 16 + g;
        #pragma unroll
        for (int nj = 0; nj < 2; nj++) {
            int cc = bn2 + wn + nj * 8 + tg * 2;
            float a0 = acc[mi][nj][0], a1 = acc[mi][nj][1];
            float a2 = acc[mi][nj][2], a3 = acc[mi][nj][3];
            float b0 = acc[mi][nj+2][0], b1 = acc[mi][nj+2][1];
            float b2 = acc[mi][nj+2][2], b3 = acc[mi][nj+2][3];
            float v0 = a0 / (1.f + __expf(-a0)) * b0;
            float v1 = a1 / (1.f + __expf(-a1)) * b1;
            float v2 = a2 / (1.f + __expf(-a2)) * b2;
            float v3 = a3 / (1.f + __expf(-a3)) * b3;
            *(__nv_bfloat162*)(G + (size_t)r0 * Dsz + cc)       = __floats2bfloat162_rn(v0, v1);
            *(__nv_bfloat162*)(G + (size_t)(r0 + 8) * Dsz + cc) = __floats2bfloat162_rn(v2, v3);
        }
    }
}

// ---------------- bf16 flash attention (exp2 + ldmatrix, 1 sync/tile) -------
#define KSTb 88
#define VSTb 136
#define KTILE (128*KSTb)
#define VTILE (64*VSTb)
#define STG_B ((KTILE+VTILE)*2)
#define MSK_B (2*STG_B)
#define AT_SMEM_BYTES (MSK_B + Lsz*4)
#define NKT (Lsz/128)

__global__ void __launch_bounds__(256, 2)
attn_bf16(const __nv_bfloat16* __restrict__ Q, const __nv_bfloat16* __restrict__ Km,
          const __nv_bfloat16* __restrict__ Vt, const float* __restrict__ mask,
          __nv_bfloat16* __restrict__ O)
{
    extern __shared__ __align__(16) char smraw[];
    float* Msk = (float*)(smraw + MSK_B);

    int bh = blockIdx.y;
    int b  = bh >> 3;
    int h  = bh & 7;
    int q0 = blockIdx.x * 128;
    int tid = threadIdx.x;
    int w = tid >> 5, lane = tid & 31;
    int g = lane >> 2, tg = lane & 3;
    int wq = w >> 1, wk = w & 1;

    int l7  = lane & 7;
    int sel8 = ((lane >> 3) & 1) << 3;   // 0 or 8

    size_t baseBL = (size_t)b * Lsz;

    #pragma unroll
    for (int i = tid; i < Lsz/4; i += 256) {
        float4 m4 = ((const float4*)(mask + baseBL))[i];
        m4.x *= LOG2E; m4.y *= LOG2E; m4.z *= LOG2E; m4.w *= LOG2E;
        ((float4*)Msk)[i] = m4;
    }

    auto prefetchKV = [&](int kt, int stg) {
        const __nv_bfloat16* Kg = Km + (baseBL + kt*128) * Dsz + h*HDsz;
        const __nv_bfloat16* Vg = Vt + ((size_t)bh * HDsz) * Lsz + kt*128;
        __nv_bfloat16* Kst = (__nv_bfloat16*)(smraw + stg * STG_B);
        __nv_bfloat16* Vst = Kst + KTILE;
        #pragma unroll
        for (int i = 0; i < 4; i++) {
            int c = tid + i * 256;
            int r = c >> 3, q8 = (c & 7) << 3;
            cp16(Kst + r*KSTb + q8, Kg + (size_t)r*Dsz + q8);
        }
        #pragma unroll
        for (int i = 0; i < 4; i++) {
            int c = tid + i * 256;
            int r = c >> 4, q8 = (c & 15) << 3;
            cp16(Vst + r*VSTb + q8, Vg + (size_t)r*Lsz + q8);
        }
    };

    prefetchKV(0, 0);
    asm volatile("cp.async.commit_group;");

    uint32_t qf[2][4][4];
    #pragma unroll
    for (int qb = 0; qb < 2; qb++) {
        const __nv_bfloat16* Qp = Q + (baseBL + q0 + wq*32 + qb*16 + g) * Dsz + h*HDsz;
        #pragma unroll
        for (int kk = 0; kk < 4; kk++) {
            qf[qb][kk][0] = *(const uint32_t*)(Qp + kk*16 + 2*tg);
            qf[qb][kk][1] = *(const uint32_t*)(Qp + 8*Dsz + kk*16 + 2*tg);
            qf[qb][kk][2] = *(const uint32_t*)(Qp + kk*16 + 2*tg + 8);
            qf[qb][kk][3] = *(const uint32_t*)(Qp + 8*Dsz + kk*16 + 2*tg + 8);
        }
    }

    float o[2][8][4];
    #pragma unroll
    for (int qb = 0; qb < 2; qb++)
        #pragma unroll
        for (int j = 0; j < 8; j++)
            #pragma unroll
            for (int r = 0; r < 4; r++) o[qb][j][r] = 0.f;
    float lp[2][2] = {{0.f, 0.f}, {0.f, 0.f}};

    for (int kt = 0; kt < NKT; kt++) {
        asm volatile("cp.async.wait_group 0;");
        __syncthreads();
        if (kt + 1 < NKT) {
            prefetchKV(kt + 1, (kt + 1) & 1);
            asm volatile("cp.async.commit_group;");
        }
        const __nv_bfloat16* Ks = (const __nv_bfloat16*)(smraw + (kt & 1) * STG_B);
        const __nv_bfloat16* Vs = Ks + KTILE;
        uint32_t Ks_u = smem_u32(Ks);
        uint32_t Vs_u = smem_u32(Vs);

        #pragma unroll
        for (int kc = 0; kc < 4; kc++) {
            float s0[2][4], s1[2][4];
            #pragma unroll
            for (int qb = 0; qb < 2; qb++)
                #pragma unroll
                for (int r = 0; r < 4; r++) { s0[qb][r] = 0.f; s1[qb][r] = 0.f; }

            int keybase = wk*64 + kc*16;
            #pragma unroll
            for (int kk = 0; kk < 4; kk++) {
                uint32_t kb0[2], kb1[2];
                ldsm_x2(kb0, Ks_u + (uint32_t)(((keybase + l7)     * KSTb + kk*16 + sel8) * 2));
                ldsm_x2(kb1, Ks_u + (uint32_t)(((keybase + 8 + l7) * KSTb + kk*16 + sel8) * 2));
                mma_bf16_16x8x16(s0[0], qf[0][kk], kb0[0], kb0[1]);
                mma_bf16_16x8x16(s0[1], qf[1][kk], kb0[0], kb0[1]);
                mma_bf16_16x8x16(s1[0], qf[0][kk], kb1[0], kb1[1]);
                mma_bf16_16x8x16(s1[1], qf[1][kk], kb1[0], kb1[1]);
            }

            float2 mk0 = *(const float2*)(Msk + kt*128 + keybase + 2*tg);
            float2 mk1 = *(const float2*)(Msk + kt*128 + keybase + 8 + 2*tg);

            uint32_t pf[2][4];
            #pragma unroll
            for (int qb = 0; qb < 2; qb++) {
                float e00 = ex2f(s0[qb][0] + mk0.x);
                float e01 = ex2f(s0[qb][1] + mk0.y);
                float e02 = ex2f(s0[qb][2] + mk0.x);
                float e03 = ex2f(s0[qb][3] + mk0.y);
                float e10 = ex2f(s1[qb][0] + mk1.x);
                float e11 = ex2f(s1[qb][1] + mk1.y);
                float e12 = ex2f(s1[qb][2] + mk1.x);
                float e13 = ex2f(s1[qb][3] + mk1.y);
                lp[qb][0] += e00 + e01 + e10 + e11;
                lp[qb][1] += e02 + e03 + e12 + e13;
                pf[qb][0] = packbf(e00, e01);
                pf[qb][1] = packbf(e02, e03);
                pf[qb][2] = packbf(e10, e11);
                pf[qb][3] = packbf(e12, e13);
            }

            #pragma unroll
            for (int j = 0; j < 8; j++) {
                uint32_t vb[2];
                ldsm_x2(vb, Vs_u + (uint32_t)(((j*8 + l7) * VSTb + keybase + sel8) * 2));
                mma_bf16_16x8x16(o[0][j], pf[0], vb[0], vb[1]);
                mma_bf16_16x8x16(o[1][j], pf[1], vb[0], vb[1]);
            }
        }
    }

    #pragma unroll
    for (int qb = 0; qb < 2; qb++)
        #pragma unroll
        for (int r = 0; r < 2; r++) {
            lp[qb][r] += __shfl_xor_sync(0xffffffffu, lp[qb][r], 1);
            lp[qb][r] += __shfl_xor_sync(0xffffffffu, lp[qb][r], 2);
        }

    __syncthreads();   // all warps past final tile before stage-0 reuse as Ex
    float* Ex = (float*)smraw;
    if (wk == 1) {
        #pragma unroll
        for (int qb = 0; qb < 2; qb++) {
            float* ep = Ex + (wq*2 + qb) * 1024;
            #pragma unroll
            for (int j = 0; j < 8; j++) {
                *(float2*)(ep + g*64     + j*8 + 2*tg) = make_float2(o[qb][j][0], o[qb][j][1]);
                *(float2*)(ep + (g+8)*64 + j*8 + 2*tg) = make_float2(o[qb][j][2], o[qb][j][3]);
            }
        }
        if (tg == 0) {
            #pragma unroll
            for (int qb = 0; qb < 2; qb++) {
                Msk[wq*32 + qb*16 + g]     = lp[qb][0];
                Msk[wq*32 + qb*16 + g + 8] = lp[qb][1];
            }
        }
    }
    __syncthreads();
    if (wk == 0) {
        #pragma unroll
        for (int qb = 0; qb < 2; qb++) {
            const float* ep = Ex + (wq*2 + qb) * 1024;
            float l0 = lp[qb][0] + Msk[wq*32 + qb*16 + g];
            float l1 = lp[qb][1] + Msk[wq*32 + qb*16 + g + 8];
            float inv0 = 1.f / l0, inv1 = 1.f / l1;
            int row = q0 + wq*32 + qb*16 + g;
            __nv_bfloat16* Op0 = O + (baseBL + row) * Dsz + h*HDsz;
            __nv_bfloat16* Op1 = Op0 + (size_t)8 * Dsz;
            #pragma unroll
            for (int j = 0; j < 8; j++) {
                float2 p0 = *(const float2*)(ep + g*64     + j*8 + 2*tg);
                float2 p1 = *(const float2*)(ep + (g+8)*64 + j*8 + 2*tg);
                *(__nv_bfloat162*)(Op0 + j*8 + 2*tg) =
                    __floats2bfloat162_rn((o[qb][j][0] + p0.x)*inv0, (o[qb][j][1] + p0.y)*inv0);
                *(__nv_bfloat162*)(Op1 + j*8 + 2*tg) =
                    __floats2bfloat162_rn((o[qb][j][2] + p1.x)*inv1, (o[qb][j][3] + p1.y)*inv1);
            }
        }
    }
}

// ---------------- host orchestration ----------------------------------------
extern "C" void kernel_launch(void* const* d_in, const int* in_sizes, int n_in,
                              void* d_out, int out_size)
{
    const float* x    = (const float*)d_in[0];
    const float* pcos = (const float*)d_in[1];
    const float* psin = (const float*)d_in[2];
    const float* mask = (const float*)d_in[3];
    const float* Wq   = (const float*)d_in[4];
    const float* Wk   = (const float*)d_in[5];
    const float* Wv   = (const float*)d_in[6];
    const float* Wo   = (const float*)d_in[7];
    const float* W1   = (const float*)d_in[8];
    const float* W2   = (const float*)d_in[9];
    const float* ln1w = (const float*)d_in[10];
    const float* ln1b = (const float*)d_in[11];
    const float* ln2w = (const float*)d_in[12];
    const float* ln2b = (const float*)d_in[13];
    const float* lnfw = (const float*)d_in[14];
    const float* lnfb = (const float*)d_in[15];
    float* out = (float*)d_out;

    float *gx;
    __nv_bfloat16 *gxn, *gq, *gk, *gvt, *gctx, *gg, *gwb;
    cudaGetSymbolAddress((void**)&gx,   g_x);
    cudaGetSymbolAddress((void**)&gxn,  g_xnb);
    cudaGetSymbolAddress((void**)&gq,   g_qb);
    cudaGetSymbolAddress((void**)&gk,   g_kb);
    cudaGetSymbolAddress((void**)&gvt,  g_vt);
    cudaGetSymbolAddress((void**)&gctx, g_ctxb);
    cudaGetSymbolAddress((void**)&gg,   g_gb);
    cudaGetSymbolAddress((void**)&gwb,  g_wb);

    cudaFuncSetAttribute(attn_bf16, cudaFuncAttributeMaxDynamicSharedMemorySize,
                         AT_SMEM_BYTES);
    cudaFuncSetAttribute(bgemm<1>, cudaFuncAttributeMaxDynamicSharedMemorySize,
                         BGEMM_SMEM);
    cudaFuncSetAttribute(bgemm_qkv, cudaFuncAttributeMaxDynamicSharedMemorySize,
                         BGEMM_SMEM);
    cudaFuncSetAttribute(bgemm_swiglu, cudaFuncAttributeMaxDynamicSharedMemorySize,
                         BGEMM_SMEM);

    wtrans_kernel<<<dim3(32, 16, 12), dim3(32, 8)>>>(Wq, Wk, Wv, Wo, W1, W2, gwb);

    dim3 g512 (Dsz / TBN, NT / TBM);      // (4, 64)
    dim3 gQKV (Dsz / TBN, NT / TBM, 3);   // (4, 64, 3)
    dim3 gSWI (Dsz / 64,  NT / TBM);      // (8, 64)
    dim3 gattn(Lsz / 128, Bsz * Hn);      // (16, 32)

    for (int i = 0; i < NLn; i++) {
        const float* xin = (i == 0) ? x : gx;
        const __nv_bfloat16* wl = gwb + (size_t)i * WL_OFF;
        ln_kernel<true><<<NT, 128>>>(xin, ln1w + i*Dsz, ln1b + i*Dsz, gxn);
        bgemm_qkv<<<gQKV, 256, BGEMM_SMEM>>>(gxn, wl, gq, gk, gvt, pcos, psin, Dsz, Dsz);
        attn_bf16<<<gattn, 256, AT_SMEM_BYTES>>>(gq, gk, gvt, mask, gctx);
        bgemm<1><<<g512, 256, BGEMM_SMEM>>>(gctx, wl + 786432, xin, gx, Dsz, Dsz);
        ln_kernel<true><<<NT, 128>>>(gx, ln2w + i*Dsz, ln2b + i*Dsz, gxn);
        bgemm_swiglu<<<gSWI, 256, BGEMM_SMEM>>>(gxn, wl + 1048576, gg, Dsz);
        bgemm<1><<<g512, 256, BGEMM_SMEM>>>(gg, wl + 1572864, gx, gx, Dsz, Dsz);
    }
    ln_kernel<false><<<NT, 128>>>(gx, lnfw, lnfb, out);
}